// round 7
// baseline (speedup 1.0000x reference)
#include <cuda_runtime.h>
#include <math.h>

#define NN 20000
#define EE 320000
#define ET_MAX (EE + NN)

// ---------------- scratch (static device globals; no allocation) ----------------
__device__ float g_h1[NN * 512];   // widest hidden buffer (msg hidden 256 / enhancer 512)
__device__ float g_x [NN * 256];   // concat x0, later conv2 output, later pre-LN
__device__ float g_xl[NN * 256];
__device__ float g_xr[NN * 256];
__device__ float g_y [NN * 256];   // conv1 output, later conv3 output
__device__ int   g_cnt[NN + 1];
__device__ int   g_off[NN + 1];
__device__ int   g_cur[NN];
__device__ int   g_esrc[ET_MAX];

// ---------------- packed f32x2 helpers (2x FFMA throughput on sm_103a) ----------
__device__ __forceinline__ unsigned long long f2pack(float a, float b) {
    unsigned long long r;
    asm("mov.b64 %0, {%1, %2};" : "=l"(r) : "f"(a), "f"(b));
    return r;
}
__device__ __forceinline__ void f2fma(unsigned long long& c, unsigned long long a,
                                      unsigned long long b) {
    asm("fma.rn.f32x2 %0, %1, %2, %3;" : "=l"(c) : "l"(a), "l"(b), "l"(c));
}
__device__ __forceinline__ float2 f2unpack(unsigned long long v) {
    float2 r;
    asm("mov.b64 {%0, %1}, %2;" : "=f"(r.x), "=f"(r.y) : "l"(v));
    return r;
}

// ---------------- SGEMM: C[M,Nout] = act(A[M,K] @ W[Nout,K]^T + bias) -----------
// 128x128 block tile, BK=8, 256 threads, 8x8 per thread via f32x2 pairs.
#define BM 128
#define BN 128
#define BK 8

__global__ __launch_bounds__(256)
void sgemm(const float* __restrict__ A, int lda,
           const float* __restrict__ W,              // [Nout, K] row-major
           const float* __restrict__ bias,           // [Nout] or nullptr
           float* __restrict__ C, int ldc, int coff,
           int M, int K, int act)
{
    __shared__ float As[BK][BM + 4];
    __shared__ float Bs[BK][BN + 4];
    const int bm   = blockIdx.y * BM;
    const int bn   = blockIdx.x * BN;
    const int tid  = threadIdx.x;
    const int tx   = tid & 15;
    const int ty   = tid >> 4;
    const int lrow = tid >> 1;
    const int lk   = (tid & 1) * 4;

    unsigned long long c2[8][4];
#pragma unroll
    for (int i = 0; i < 8; i++)
#pragma unroll
        for (int j = 0; j < 4; j++) c2[i][j] = 0ULL;

    const int   arow   = bm + lrow;
    const bool  avalid = (arow < M);
    const float* Ap = A + (size_t)arow * lda + lk;
    const float* Wp = W + (size_t)(bn + lrow) * K + lk;

    for (int k0 = 0; k0 < K; k0 += BK) {
        float4 av = avalid ? *(const float4*)(Ap + k0) : make_float4(0.f, 0.f, 0.f, 0.f);
        float4 wv = *(const float4*)(Wp + k0);
        As[lk + 0][lrow] = av.x; As[lk + 1][lrow] = av.y;
        As[lk + 2][lrow] = av.z; As[lk + 3][lrow] = av.w;
        Bs[lk + 0][lrow] = wv.x; Bs[lk + 1][lrow] = wv.y;
        Bs[lk + 2][lrow] = wv.z; Bs[lk + 3][lrow] = wv.w;
        __syncthreads();
#pragma unroll
        for (int k = 0; k < BK; k++) {
            float4 a0 = *(const float4*)&As[k][ty * 8];
            float4 a1 = *(const float4*)&As[k][ty * 8 + 4];
            unsigned long long avv[8];
            avv[0] = f2pack(a0.x, a0.x); avv[1] = f2pack(a0.y, a0.y);
            avv[2] = f2pack(a0.z, a0.z); avv[3] = f2pack(a0.w, a0.w);
            avv[4] = f2pack(a1.x, a1.x); avv[5] = f2pack(a1.y, a1.y);
            avv[6] = f2pack(a1.z, a1.z); avv[7] = f2pack(a1.w, a1.w);
            const unsigned long long* bp = (const unsigned long long*)&Bs[k][tx * 8];
            unsigned long long bv[4] = {bp[0], bp[1], bp[2], bp[3]};
#pragma unroll
            for (int i = 0; i < 8; i++)
#pragma unroll
                for (int j = 0; j < 4; j++) f2fma(c2[i][j], avv[i], bv[j]);
        }
        __syncthreads();
    }

#pragma unroll
    for (int i = 0; i < 8; i++) {
        int row = bm + ty * 8 + i;
        if (row >= M) continue;
        float* Cp = C + (size_t)row * ldc + coff + bn + tx * 8;
#pragma unroll
        for (int j = 0; j < 4; j++) {
            float2 v = f2unpack(c2[i][j]);
            if (bias) {
                int col = bn + tx * 8 + 2 * j;
                v.x += bias[col];
                v.y += bias[col + 1];
            }
            if (act) { v.x = fmaxf(v.x, 0.f); v.y = fmaxf(v.y, 0.f); }
            *(float2*)(Cp + 2 * j) = v;
        }
    }
}

// ---------------- CSR build (by dst, includes self-loops) -----------------------
__global__ void k_zero(int* __restrict__ p, int n) {
    int i = blockIdx.x * blockDim.x + threadIdx.x;
    if (i < n) p[i] = 0;
}
__global__ void k_count(const int* __restrict__ ei, int E, int n, int* __restrict__ cnt) {
    int i = blockIdx.x * blockDim.x + threadIdx.x;
    if (i >= E + n) return;
    int d = (i < E) ? ei[E + i] : (i - E);
    atomicAdd(&cnt[d], 1);
}
__global__ void k_scan(const int* __restrict__ cnt, int* __restrict__ off,
                       int* __restrict__ cur, int n)
{
    __shared__ int sh[1024];
    __shared__ int s_carry;
    if (threadIdx.x == 0) s_carry = 0;
    __syncthreads();
    for (int base = 0; base < n; base += 1024) {
        int i = base + (int)threadIdx.x;
        int v = (i < n) ? cnt[i] : 0;
        sh[threadIdx.x] = v;
        __syncthreads();
        for (int o = 1; o < 1024; o <<= 1) {
            int t = (threadIdx.x >= (unsigned)o) ? sh[threadIdx.x - o] : 0;
            __syncthreads();
            sh[threadIdx.x] += t;
            __syncthreads();
        }
        int excl = s_carry + sh[threadIdx.x] - v;
        if (i < n) { off[i] = excl; cur[i] = excl; }
        __syncthreads();
        if (threadIdx.x == 0) s_carry += sh[1023];
        __syncthreads();
    }
    if (threadIdx.x == 0) off[n] = s_carry;
}
__global__ void k_scatter(const int* __restrict__ ei, int E, int n,
                          int* __restrict__ cur, int* __restrict__ esrc)
{
    int i = blockIdx.x * blockDim.x + threadIdx.x;
    if (i >= E + n) return;
    int s, d;
    if (i < E) { s = ei[i]; d = ei[E + i]; } else { s = d = i - E; }
    int pos = atomicAdd(&cur[d], 1);
    esrc[pos] = s;
}

// ---------------- fused GATv2 edge aggregation (warp per dst node) --------------
// One pass over incoming edges with online softmax: each xl[src] row is read once
// and reused for both the attention logit and the weighted accumulation.
template <int H, int C, bool RELU>
__global__ void gat_agg(const float* __restrict__ xl, const float* __restrict__ xr,
                        const float* __restrict__ att, const float* __restrict__ bias,
                        const int* __restrict__ off, const int* __restrict__ esrc,
                        float* __restrict__ out, int n)
{
    constexpr int HC = H * C;
    constexpr int R  = HC / 32;   // channels per thread (8 or 4)
    constexpr int G  = C / R;     // threads per head (8, 16, 32)
    int gw = (blockIdx.x * blockDim.x + threadIdx.x) >> 5;
    if (gw >= n) return;
    int lane = threadIdx.x & 31;
    int ch0  = lane * R;

    float xrd[R], attv[R], acc[R];
#pragma unroll
    for (int q = 0; q < R / 4; q++) {
        float4 t = *(const float4*)(xr + (size_t)gw * HC + ch0 + q * 4);
        xrd[q * 4 + 0] = t.x; xrd[q * 4 + 1] = t.y;
        xrd[q * 4 + 2] = t.z; xrd[q * 4 + 3] = t.w;
        float4 a = *(const float4*)(att + ch0 + q * 4);
        attv[q * 4 + 0] = a.x; attv[q * 4 + 1] = a.y;
        attv[q * 4 + 2] = a.z; attv[q * 4 + 3] = a.w;
    }
#pragma unroll
    for (int r = 0; r < R; r++) acc[r] = 0.f;

    float m = __int_as_float(0xff800000);  // -inf
    float denom = 0.f;
    int beg = off[gw], end = off[gw + 1];
    for (int j = beg; j < end; j++) {
        int s = esrc[j];
        const float4* p = (const float4*)(xl + (size_t)s * HC + ch0);
        float v[R];
        float partial = 0.f;
#pragma unroll
        for (int q = 0; q < R / 4; q++) {
            float4 t = p[q];
            v[q * 4 + 0] = t.x; v[q * 4 + 1] = t.y;
            v[q * 4 + 2] = t.z; v[q * 4 + 3] = t.w;
        }
#pragma unroll
        for (int r = 0; r < R; r++) {
            float e = v[r] + xrd[r];
            e = e > 0.f ? e : 0.2f * e;       // leaky_relu(0.2)
            partial = fmaf(e, attv[r], partial);
        }
#pragma unroll
        for (int o = G / 2; o > 0; o >>= 1)
            partial += __shfl_xor_sync(0xffffffffu, partial, o);
        // online softmax update (branch uniform within head group)
        if (partial > m) {
            float sc = __expf(m - partial);   // exp(-inf)=0 on first edge
            denom = denom * sc + 1.f;
#pragma unroll
            for (int r = 0; r < R; r++) acc[r] = fmaf(acc[r], sc, v[r]);
            m = partial;
        } else {
            float p2 = __expf(partial - m);
            denom += p2;
#pragma unroll
            for (int r = 0; r < R; r++) acc[r] = fmaf(p2, v[r], acc[r]);
        }
    }
    float inv = 1.f / denom;
#pragma unroll
    for (int q = 0; q < R / 4; q++) {
        float4 o;
        o.x = acc[q * 4 + 0] * inv + bias[ch0 + q * 4 + 0];
        o.y = acc[q * 4 + 1] * inv + bias[ch0 + q * 4 + 1];
        o.z = acc[q * 4 + 2] * inv + bias[ch0 + q * 4 + 2];
        o.w = acc[q * 4 + 3] * inv + bias[ch0 + q * 4 + 3];
        if (RELU) {
            o.x = fmaxf(o.x, 0.f); o.y = fmaxf(o.y, 0.f);
            o.z = fmaxf(o.z, 0.f); o.w = fmaxf(o.w, 0.f);
        }
        *(float4*)(out + (size_t)gw * HC + ch0 + q * 4) = o;
    }
}

// ---------------- LayerNorm over 256 channels (warp per row) --------------------
__global__ void k_ln(const float* __restrict__ x, const float* __restrict__ gg,
                     const float* __restrict__ bb, float* __restrict__ out, int n)
{
    int w = (blockIdx.x * blockDim.x + threadIdx.x) >> 5;
    if (w >= n) return;
    int lane = threadIdx.x & 31;
    const float4* p = (const float4*)(x + (size_t)w * 256) + lane * 2;
    float4 a = p[0], b = p[1];
    float s = a.x + a.y + a.z + a.w + b.x + b.y + b.z + b.w;
#pragma unroll
    for (int o = 16; o > 0; o >>= 1) s += __shfl_xor_sync(0xffffffffu, s, o);
    float mu = s * (1.f / 256.f);
    float q = 0.f;
    q = fmaf(a.x - mu, a.x - mu, q); q = fmaf(a.y - mu, a.y - mu, q);
    q = fmaf(a.z - mu, a.z - mu, q); q = fmaf(a.w - mu, a.w - mu, q);
    q = fmaf(b.x - mu, b.x - mu, q); q = fmaf(b.y - mu, b.y - mu, q);
    q = fmaf(b.z - mu, b.z - mu, q); q = fmaf(b.w - mu, b.w - mu, q);
#pragma unroll
    for (int o = 16; o > 0; o >>= 1) q += __shfl_xor_sync(0xffffffffu, q, o);
    float rs = rsqrtf(q * (1.f / 256.f) + 1e-5f);
    int ch = lane * 8;
    float4 g0 = *(const float4*)(gg + ch), g1 = *(const float4*)(gg + ch + 4);
    float4 b0 = *(const float4*)(bb + ch), b1 = *(const float4*)(bb + ch + 4);
    float4 o0, o1;
    o0.x = (a.x - mu) * rs * g0.x + b0.x; o0.y = (a.y - mu) * rs * g0.y + b0.y;
    o0.z = (a.z - mu) * rs * g0.z + b0.z; o0.w = (a.w - mu) * rs * g0.w + b0.w;
    o1.x = (b.x - mu) * rs * g1.x + b1.x; o1.y = (b.y - mu) * rs * g1.y + b1.y;
    o1.z = (b.z - mu) * rs * g1.z + b1.z; o1.w = (b.w - mu) * rs * g1.w + b1.w;
    float4* op = (float4*)(out + (size_t)w * 256) + lane * 2;
    op[0] = o0; op[1] = o1;
}

// ---------------- launch ---------------------------------------------------------
extern "C" void kernel_launch(void* const* d_in, const int* in_sizes, int n_in,
                              void* d_out, int out_size)
{
    const float* node_f = (const float*)d_in[0];
    const float* msg_f  = (const float*)d_in[1];
    const int*   ei     = (const int*)d_in[2];
    const float* me_w1  = (const float*)d_in[3];
    const float* me_b1  = (const float*)d_in[4];
    const float* me_w2  = (const float*)d_in[5];
    const float* me_b2  = (const float*)d_in[6];
    const float* ne_w1  = (const float*)d_in[7];
    const float* ne_b1  = (const float*)d_in[8];
    const float* ne_w2  = (const float*)d_in[9];
    const float* ne_b2  = (const float*)d_in[10];
    const float* c1_wl  = (const float*)d_in[11];
    const float* c1_wr  = (const float*)d_in[12];
    const float* c1_att = (const float*)d_in[13];
    const float* c1_b   = (const float*)d_in[14];
    const float* c2_wl  = (const float*)d_in[15];
    const float* c2_wr  = (const float*)d_in[16];
    const float* c2_att = (const float*)d_in[17];
    const float* c2_b   = (const float*)d_in[18];
    const float* c3_wl  = (const float*)d_in[19];
    const float* c3_wr  = (const float*)d_in[20];
    const float* c3_att = (const float*)d_in[21];
    const float* c3_b   = (const float*)d_in[22];
    const float* en_w1  = (const float*)d_in[23];
    const float* en_b1  = (const float*)d_in[24];
    const float* en_w2  = (const float*)d_in[25];
    const float* en_b2  = (const float*)d_in[26];
    const float* ln_g   = (const float*)d_in[27];
    const float* ln_b   = (const float*)d_in[28];

    const int n = in_sizes[0] / 128;
    const int E = in_sizes[2] / 2;

    float *h1, *x, *xl, *xr, *y;
    int *cnt, *off, *cur, *esrc;
    cudaGetSymbolAddress((void**)&h1,   g_h1);
    cudaGetSymbolAddress((void**)&x,    g_x);
    cudaGetSymbolAddress((void**)&xl,   g_xl);
    cudaGetSymbolAddress((void**)&xr,   g_xr);
    cudaGetSymbolAddress((void**)&y,    g_y);
    cudaGetSymbolAddress((void**)&cnt,  g_cnt);
    cudaGetSymbolAddress((void**)&off,  g_off);
    cudaGetSymbolAddress((void**)&cur,  g_cur);
    cudaGetSymbolAddress((void**)&esrc, g_esrc);

    const int et = E + n;
    k_zero   <<<(n + 1 + 255) / 256, 256>>>(cnt, n + 1);
    k_count  <<<(et + 255) / 256, 256>>>(ei, E, n, cnt);
    k_scan   <<<1, 1024>>>(cnt, off, cur, n);
    k_scatter<<<(et + 255) / 256, 256>>>(ei, E, n, cur, esrc);

    dim3 blk(256);
    auto gemm = [&](const float* A, int lda, const float* W, const float* bias,
                    float* Cc, int ldc, int coff, int Nout, int K, int act) {
        dim3 grid(Nout / 128, (n + 127) / 128);
        sgemm<<<grid, blk>>>(A, lda, W, bias, Cc, ldc, coff, n, K, act);
    };

    // encoders -> x = concat(node_emb, msg_emb)  [N,256]
    gemm(msg_f, 256, me_w1, me_b1, h1, 256,   0, 256, 256, 1);
    gemm(h1,    256, me_w2, me_b2, x,  256, 128, 128, 256, 0);
    gemm(node_f,128, ne_w1, ne_b1, h1, 128,   0, 128, 128, 1);
    gemm(h1,    128, ne_w2, ne_b2, x,  256,   0, 128, 128, 0);

    const int gat_blocks = (n * 32 + 255) / 256;

    // conv1: 256 -> 4x64 concat, relu
    gemm(x, 256, c1_wl, nullptr, xl, 256, 0, 256, 256, 0);
    gemm(x, 256, c1_wr, nullptr, xr, 256, 0, 256, 256, 0);
    gat_agg<4, 64, true><<<gat_blocks, 256>>>(xl, xr, c1_att, c1_b, off, esrc, y, n);

    // conv2: 256 -> 2x64 concat, relu
    gemm(y, 256, c2_wl, nullptr, xl, 128, 0, 128, 256, 0);
    gemm(y, 256, c2_wr, nullptr, xr, 128, 0, 128, 256, 0);
    gat_agg<2, 64, true><<<gat_blocks, 256>>>(xl, xr, c2_att, c2_b, off, esrc, x, n);

    // conv3: 128 -> 1x256, mean over 1 head == identity, no relu
    gemm(x, 128, c3_wl, nullptr, xl, 256, 0, 256, 128, 0);
    gemm(x, 128, c3_wr, nullptr, xr, 256, 0, 256, 128, 0);
    gat_agg<1, 256, false><<<gat_blocks, 256>>>(xl, xr, c3_att, c3_b, off, esrc, y, n);

    // enhancer MLP + LayerNorm
    gemm(y,  256, en_w1, en_b1, h1, 512, 0, 512, 256, 1);
    gemm(h1, 512, en_w2, en_b2, x,  256, 0, 256, 512, 0);
    k_ln<<<gat_blocks, 256>>>(x, ln_g, ln_b, (float*)d_out, n);
}

// round 10
// speedup vs baseline: 1.6694x; 1.6694x over previous
#include <cuda_runtime.h>
#include <cuda_bf16.h>
#include <cstdint>
#include <math.h>

#define NN 20000
#define EE 320000
#define ET_MAX (EE + NN)

// ---------------- scratch (static device globals; no allocation) ----------------
__device__ float g_h1[NN * 512];
__device__ float g_x [NN * 256];
__device__ float g_xl[NN * 256];
__device__ float g_xr[NN * 256];
__device__ float g_y [NN * 256];
__device__ int   g_cnt[NN + 1];
__device__ int   g_off[NN + 1];
__device__ int   g_cur[NN];
__device__ int   g_esrc[ET_MAX];

// ================= warp-level tensor-core helpers (sm_80+ PTX, arch-agnostic) ===
__device__ __forceinline__ uint32_t smem_u32(const void* p) {
    uint32_t a;
    asm("{ .reg .u64 t; cvta.to.shared.u64 t, %1; cvt.u32.u64 %0, t; }" : "=r"(a) : "l"(p));
    return a;
}
__device__ __forceinline__ void ldm_x4(uint32_t addr, uint32_t& r0, uint32_t& r1,
                                       uint32_t& r2, uint32_t& r3) {
    asm volatile("ldmatrix.sync.aligned.m8n8.x4.shared.b16 {%0,%1,%2,%3}, [%4];"
                 : "=r"(r0), "=r"(r1), "=r"(r2), "=r"(r3) : "r"(addr));
}
__device__ __forceinline__ void mma_bf16(float* d, const uint32_t* a, const uint32_t* b) {
    asm volatile(
        "mma.sync.aligned.m16n8k16.row.col.f32.bf16.bf16.f32 "
        "{%0,%1,%2,%3}, {%4,%5,%6,%7}, {%8,%9}, {%0,%1,%2,%3};"
        : "+f"(d[0]), "+f"(d[1]), "+f"(d[2]), "+f"(d[3])
        : "r"(a[0]), "r"(a[1]), "r"(a[2]), "r"(a[3]), "r"(b[0]), "r"(b[1]));
}

// ================= split-bf16 tensor-core GEMM ==================================
// C[M,Nout] = act(A[M,K] @ W[Nout,K]^T + bias), fp32 in/out.
// fp32 = hi + lo bf16; D += Ahi*Bhi + Ahi*Blo + Alo*Bhi (fp32 register accum).
// CTA: 128x128 tile, KT=64, 256 threads (8 warps, each 32x64).
#define KT 64
#define TS 72                       /* smem row stride in bf16 elts (144B) */
#define TILE_BYTES (128 * TS * 2)   /* 18432 */
#define SA_HI 0
#define SA_LO TILE_BYTES
#define SB_HI (2 * TILE_BYTES)
#define SB_LO (3 * TILE_BYTES)
#define GEMM_SMEM (4 * TILE_BYTES)  /* 73728 */

__device__ __forceinline__ void stage_hilo(char* smem, int offHi, int offLo,
                                           int row, int c8, float4 v0, float4 v1) {
    __nv_bfloat162 h0 = __float22bfloat162_rn(make_float2(v0.x, v0.y));
    __nv_bfloat162 h1 = __float22bfloat162_rn(make_float2(v0.z, v0.w));
    __nv_bfloat162 h2 = __float22bfloat162_rn(make_float2(v1.x, v1.y));
    __nv_bfloat162 h3 = __float22bfloat162_rn(make_float2(v1.z, v1.w));
    float2 f0 = __bfloat1622float2(h0), f1 = __bfloat1622float2(h1);
    float2 f2 = __bfloat1622float2(h2), f3 = __bfloat1622float2(h3);
    __nv_bfloat162 l0 = __float22bfloat162_rn(make_float2(v0.x - f0.x, v0.y - f0.y));
    __nv_bfloat162 l1 = __float22bfloat162_rn(make_float2(v0.z - f1.x, v0.w - f1.y));
    __nv_bfloat162 l2 = __float22bfloat162_rn(make_float2(v1.x - f2.x, v1.y - f2.y));
    __nv_bfloat162 l3 = __float22bfloat162_rn(make_float2(v1.z - f3.x, v1.w - f3.y));
    int byte = (row * TS + c8) * 2;
    *(uint4*)(smem + offHi + byte) = make_uint4(*(uint32_t*)&h0, *(uint32_t*)&h1,
                                                *(uint32_t*)&h2, *(uint32_t*)&h3);
    *(uint4*)(smem + offLo + byte) = make_uint4(*(uint32_t*)&l0, *(uint32_t*)&l1,
                                                *(uint32_t*)&l2, *(uint32_t*)&l3);
}

__global__ __launch_bounds__(256, 2)
void gemm_mma(const float* __restrict__ A, int lda,
              const float* __restrict__ W,            // [Nout, K] row-major
              const float* __restrict__ bias,         // nullable
              float* __restrict__ C, int ldc, int coff,
              int M, int K, int act)
{
    extern __shared__ char smem[];
    const uint32_t sb = smem_u32(smem);
    const int tid  = threadIdx.x;
    const int lane = tid & 31;
    const int wid  = tid >> 5;
    const int bm = blockIdx.y * 128;
    const int bn = blockIdx.x * 128;
    const int wm = (wid & 3) * 32;        // warp row offset within CTA tile
    const int wn = (wid >> 2) * 64;       // warp col offset within CTA tile

    float d[2][8][4];
#pragma unroll
    for (int mt = 0; mt < 2; mt++)
#pragma unroll
        for (int nt = 0; nt < 8; nt++)
#pragma unroll
            for (int r = 0; r < 4; r++) d[mt][nt][r] = 0.f;

    // per-lane ldmatrix addressing components
    const int a_row  = wm + (lane & 15);
    const int a_colo = (lane >> 4) << 3;
    const int b_row  = wn + ((lane >> 4) << 3) + (lane & 7);
    const int b_colo = ((lane >> 3) & 1) << 3;

    for (int kt = 0; kt < K; kt += KT) {
        // ---- stage A tile (128 x 64), fused fp32 -> hi/lo bf16
        for (int t = tid; t < 1024; t += 256) {
            int row = t >> 3, c8 = (t & 7) << 3;
            int gr = bm + row;
            float4 v0, v1;
            if (gr < M) {
                const float* p = A + (size_t)gr * lda + kt + c8;
                v0 = *(const float4*)p;
                v1 = *(const float4*)(p + 4);
            } else {
                v0 = make_float4(0.f, 0.f, 0.f, 0.f);
                v1 = v0;
            }
            stage_hilo(smem, SA_HI, SA_LO, row, c8, v0, v1);
        }
        // ---- stage B tile (rows bn..bn+127 of W, 64 K-cols)
        for (int t = tid; t < 1024; t += 256) {
            int row = t >> 3, c8 = (t & 7) << 3;
            const float* p = W + (size_t)(bn + row) * K + kt + c8;
            float4 v0 = *(const float4*)p;
            float4 v1 = *(const float4*)(p + 4);
            stage_hilo(smem, SB_HI, SB_LO, row, c8, v0, v1);
        }
        __syncthreads();

#pragma unroll
        for (int pass = 0; pass < 3; pass++) {
            const uint32_t abase = sb + ((pass == 2) ? SA_LO : SA_HI);
            const uint32_t bbase = sb + ((pass == 1) ? SB_LO : SB_HI);
#pragma unroll
            for (int k0 = 0; k0 < KT; k0 += 16) {
                uint32_t a[2][4];
#pragma unroll
                for (int mt = 0; mt < 2; mt++)
                    ldm_x4(abase + ((a_row + mt * 16) * TS + k0 + a_colo) * 2,
                           a[mt][0], a[mt][1], a[mt][2], a[mt][3]);
                uint32_t b[8][2];
#pragma unroll
                for (int nt2 = 0; nt2 < 4; nt2++) {
                    uint32_t r0, r1, r2, r3;
                    ldm_x4(bbase + ((b_row + nt2 * 16) * TS + k0 + b_colo) * 2,
                           r0, r1, r2, r3);
                    b[2 * nt2][0] = r0; b[2 * nt2][1] = r1;
                    b[2 * nt2 + 1][0] = r2; b[2 * nt2 + 1][1] = r3;
                }
#pragma unroll
                for (int mt = 0; mt < 2; mt++)
#pragma unroll
                    for (int nt = 0; nt < 8; nt++)
                        mma_bf16(d[mt][nt], a[mt], b[nt]);
            }
        }
        __syncthreads();
    }

    // ---- epilogue: fragment layout lane l -> row g=l>>2 (and g+8), cols (l&3)*2..+1
    const int g  = lane >> 2;
    const int c2 = (lane & 3) * 2;
#pragma unroll
    for (int mt = 0; mt < 2; mt++) {
        int row0 = bm + wm + mt * 16 + g;
#pragma unroll
        for (int half = 0; half < 2; half++) {
            int row = row0 + half * 8;
            if (row >= M) continue;
            float* Cp = C + (size_t)row * ldc + coff;
#pragma unroll
            for (int nt = 0; nt < 8; nt++) {
                int col = bn + wn + nt * 8 + c2;
                float2 v;
                v.x = d[mt][nt][half * 2 + 0];
                v.y = d[mt][nt][half * 2 + 1];
                if (bias) { v.x += bias[col]; v.y += bias[col + 1]; }
                if (act)  { v.x = fmaxf(v.x, 0.f); v.y = fmaxf(v.y, 0.f); }
                *(float2*)(Cp + col) = v;
            }
        }
    }
}

// ---------------- CSR build (by dst, includes self-loops) -----------------------
__global__ void k_zero(int* __restrict__ p, int n) {
    int i = blockIdx.x * blockDim.x + threadIdx.x;
    if (i < n) p[i] = 0;
}
__global__ void k_count(const int* __restrict__ ei, int E, int n, int* __restrict__ cnt) {
    int i = blockIdx.x * blockDim.x + threadIdx.x;
    if (i >= E + n) return;
    int d = (i < E) ? ei[E + i] : (i - E);
    atomicAdd(&cnt[d], 1);
}
__global__ void k_scan(const int* __restrict__ cnt, int* __restrict__ off,
                       int* __restrict__ cur, int n)
{
    __shared__ int ssum[1024];
    const int t = threadIdx.x;
    const int chunk = (n + 1023) >> 10;
    const int b = t * chunk;
    int s = 0;
    for (int i = 0; i < chunk; i++) {
        int idx = b + i;
        if (idx < n) s += cnt[idx];
    }
    ssum[t] = s;
    __syncthreads();
    for (int o = 1; o < 1024; o <<= 1) {
        int v = (t >= o) ? ssum[t - o] : 0;
        __syncthreads();
        ssum[t] += v;
        __syncthreads();
    }
    int excl = ssum[t] - s;
    for (int i = 0; i < chunk; i++) {
        int idx = b + i;
        if (idx < n) {
            off[idx] = excl;
            cur[idx] = excl;
            excl += cnt[idx];
        }
    }
    if (t == 1023) off[n] = ssum[1023];
}
__global__ void k_scatter(const int* __restrict__ ei, int E, int n,
                          int* __restrict__ cur, int* __restrict__ esrc)
{
    int i = blockIdx.x * blockDim.x + threadIdx.x;
    if (i >= E + n) return;
    int s, d;
    if (i < E) { s = ei[i]; d = ei[E + i]; } else { s = d = i - E; }
    int pos = atomicAdd(&cur[d], 1);
    esrc[pos] = s;
}

// ---------------- fused GATv2 edge aggregation (warp per dst node) --------------
template <int H, int C, bool RELU>
__global__ void gat_agg(const float* __restrict__ xl, const float* __restrict__ xr,
                        const float* __restrict__ att, const float* __restrict__ bias,
                        const int* __restrict__ off, const int* __restrict__ esrc,
                        float* __restrict__ out, int n)
{
    constexpr int HC = H * C;
    constexpr int R  = HC / 32;
    constexpr int G  = C / R;
    int gw = (blockIdx.x * blockDim.x + threadIdx.x) >> 5;
    if (gw >= n) return;
    int lane = threadIdx.x & 31;
    int ch0  = lane * R;

    float xrd[R], attv[R], acc[R];
#pragma unroll
    for (int q = 0; q < R / 4; q++) {
        float4 t = *(const float4*)(xr + (size_t)gw * HC + ch0 + q * 4);
        xrd[q * 4 + 0] = t.x; xrd[q * 4 + 1] = t.y;
        xrd[q * 4 + 2] = t.z; xrd[q * 4 + 3] = t.w;
        float4 a = *(const float4*)(att + ch0 + q * 4);
        attv[q * 4 + 0] = a.x; attv[q * 4 + 1] = a.y;
        attv[q * 4 + 2] = a.z; attv[q * 4 + 3] = a.w;
    }
#pragma unroll
    for (int r = 0; r < R; r++) acc[r] = 0.f;

    float m = __int_as_float(0xff800000);
    float denom = 0.f;
    int beg = off[gw], end = off[gw + 1];
    for (int j = beg; j < end; j++) {
        int s = esrc[j];
        const float4* p = (const float4*)(xl + (size_t)s * HC + ch0);
        float v[R];
        float partial = 0.f;
#pragma unroll
        for (int q = 0; q < R / 4; q++) {
            float4 t = p[q];
            v[q * 4 + 0] = t.x; v[q * 4 + 1] = t.y;
            v[q * 4 + 2] = t.z; v[q * 4 + 3] = t.w;
        }
#pragma unroll
        for (int r = 0; r < R; r++) {
            float e = v[r] + xrd[r];
            e = e > 0.f ? e : 0.2f * e;
            partial = fmaf(e, attv[r], partial);
        }
#pragma unroll
        for (int o = G / 2; o > 0; o >>= 1)
            partial += __shfl_xor_sync(0xffffffffu, partial, o);
        if (partial > m) {
            float sc = __expf(m - partial);
            denom = denom * sc + 1.f;
#pragma unroll
            for (int r = 0; r < R; r++) acc[r] = fmaf(acc[r], sc, v[r]);
            m = partial;
        } else {
            float p2 = __expf(partial - m);
            denom += p2;
#pragma unroll
            for (int r = 0; r < R; r++) acc[r] = fmaf(p2, v[r], acc[r]);
        }
    }
    float inv = 1.f / denom;
#pragma unroll
    for (int q = 0; q < R / 4; q++) {
        float4 o;
        o.x = acc[q * 4 + 0] * inv + bias[ch0 + q * 4 + 0];
        o.y = acc[q * 4 + 1] * inv + bias[ch0 + q * 4 + 1];
        o.z = acc[q * 4 + 2] * inv + bias[ch0 + q * 4 + 2];
        o.w = acc[q * 4 + 3] * inv + bias[ch0 + q * 4 + 3];
        if (RELU) {
            o.x = fmaxf(o.x, 0.f); o.y = fmaxf(o.y, 0.f);
            o.z = fmaxf(o.z, 0.f); o.w = fmaxf(o.w, 0.f);
        }
        *(float4*)(out + (size_t)gw * HC + ch0 + q * 4) = o;
    }
}

// ---------------- LayerNorm over 256 channels (warp per row) --------------------
__global__ void k_ln(const float* __restrict__ x, const float* __restrict__ gg,
                     const float* __restrict__ bb, float* __restrict__ out, int n)
{
    int w = (blockIdx.x * blockDim.x + threadIdx.x) >> 5;
    if (w >= n) return;
    int lane = threadIdx.x & 31;
    const float4* p = (const float4*)(x + (size_t)w * 256) + lane * 2;
    float4 a = p[0], b = p[1];
    float s = a.x + a.y + a.z + a.w + b.x + b.y + b.z + b.w;
#pragma unroll
    for (int o = 16; o > 0; o >>= 1) s += __shfl_xor_sync(0xffffffffu, s, o);
    float mu = s * (1.f / 256.f);
    float q = 0.f;
    q = fmaf(a.x - mu, a.x - mu, q); q = fmaf(a.y - mu, a.y - mu, q);
    q = fmaf(a.z - mu, a.z - mu, q); q = fmaf(a.w - mu, a.w - mu, q);
    q = fmaf(b.x - mu, b.x - mu, q); q = fmaf(b.y - mu, b.y - mu, q);
    q = fmaf(b.z - mu, b.z - mu, q); q = fmaf(b.w - mu, b.w - mu, q);
#pragma unroll
    for (int o = 16; o > 0; o >>= 1) q += __shfl_xor_sync(0xffffffffu, q, o);
    float rs = rsqrtf(q * (1.f / 256.f) + 1e-5f);
    int ch = lane * 8;
    float4 g0 = *(const float4*)(gg + ch), g1 = *(const float4*)(gg + ch + 4);
    float4 b0 = *(const float4*)(bb + ch), b1 = *(const float4*)(bb + ch + 4);
    float4 o0, o1;
    o0.x = (a.x - mu) * rs * g0.x + b0.x; o0.y = (a.y - mu) * rs * g0.y + b0.y;
    o0.z = (a.z - mu) * rs * g0.z + b0.z; o0.w = (a.w - mu) * rs * g0.w + b0.w;
    o1.x = (b.x - mu) * rs * g1.x + b1.x; o1.y = (b.y - mu) * rs * g1.y + b1.y;
    o1.z = (b.z - mu) * rs * g1.z + b1.z; o1.w = (b.w - mu) * rs * g1.w + b1.w;
    float4* op = (float4*)(out + (size_t)w * 256) + lane * 2;
    op[0] = o0; op[1] = o1;
}

// ---------------- launch ---------------------------------------------------------
extern "C" void kernel_launch(void* const* d_in, const int* in_sizes, int n_in,
                              void* d_out, int out_size)
{
    const float* node_f = (const float*)d_in[0];
    const float* msg_f  = (const float*)d_in[1];
    const int*   ei     = (const int*)d_in[2];
    const float* me_w1  = (const float*)d_in[3];
    const float* me_b1  = (const float*)d_in[4];
    const float* me_w2  = (const float*)d_in[5];
    const float* me_b2  = (const float*)d_in[6];
    const float* ne_w1  = (const float*)d_in[7];
    const float* ne_b1  = (const float*)d_in[8];
    const float* ne_w2  = (const float*)d_in[9];
    const float* ne_b2  = (const float*)d_in[10];
    const float* c1_wl  = (const float*)d_in[11];
    const float* c1_wr  = (const float*)d_in[12];
    const float* c1_att = (const float*)d_in[13];
    const float* c1_b   = (const float*)d_in[14];
    const float* c2_wl  = (const float*)d_in[15];
    const float* c2_wr  = (const float*)d_in[16];
    const float* c2_att = (const float*)d_in[17];
    const float* c2_b   = (const float*)d_in[18];
    const float* c3_wl  = (const float*)d_in[19];
    const float* c3_wr  = (const float*)d_in[20];
    const float* c3_att = (const float*)d_in[21];
    const float* c3_b   = (const float*)d_in[22];
    const float* en_w1  = (const float*)d_in[23];
    const float* en_b1  = (const float*)d_in[24];
    const float* en_w2  = (const float*)d_in[25];
    const float* en_b2  = (const float*)d_in[26];
    const float* ln_g   = (const float*)d_in[27];
    const float* ln_b   = (const float*)d_in[28];

    const int n = in_sizes[0] / 128;
    const int E = in_sizes[2] / 2;

    float *h1, *x, *xl, *xr, *y;
    int *cnt, *off, *cur, *esrc;
    cudaGetSymbolAddress((void**)&h1,   g_h1);
    cudaGetSymbolAddress((void**)&x,    g_x);
    cudaGetSymbolAddress((void**)&xl,   g_xl);
    cudaGetSymbolAddress((void**)&xr,   g_xr);
    cudaGetSymbolAddress((void**)&y,    g_y);
    cudaGetSymbolAddress((void**)&cnt,  g_cnt);
    cudaGetSymbolAddress((void**)&off,  g_off);
    cudaGetSymbolAddress((void**)&cur,  g_cur);
    cudaGetSymbolAddress((void**)&esrc, g_esrc);

    cudaFuncSetAttribute(gemm_mma, cudaFuncAttributeMaxDynamicSharedMemorySize, GEMM_SMEM);

    const int et = E + n;
    k_zero   <<<(n + 1 + 255) / 256, 256>>>(cnt, n + 1);
    k_count  <<<(et + 255) / 256, 256>>>(ei, E, n, cnt);
    k_scan   <<<1, 1024>>>(cnt, off, cur, n);
    k_scatter<<<(et + 255) / 256, 256>>>(ei, E, n, cur, esrc);

    auto gemm = [&](const float* A, int lda, const float* W, const float* bias,
                    float* Cc, int ldc, int coff, int Nout, int K, int act) {
        dim3 grid(Nout / 128, (n + 127) / 128);
        gemm_mma<<<grid, 256, GEMM_SMEM>>>(A, lda, W, bias, Cc, ldc, coff, n, K, act);
    };

    // encoders -> x = concat(node_emb, msg_emb)  [N,256]
    gemm(msg_f, 256, me_w1, me_b1, h1, 256,   0, 256, 256, 1);
    gemm(h1,    256, me_w2, me_b2, x,  256, 128, 128, 256, 0);
    gemm(node_f,128, ne_w1, ne_b1, h1, 128,   0, 128, 128, 1);
    gemm(h1,    128, ne_w2, ne_b2, x,  256,   0, 128, 128, 0);

    const int gat_blocks = (n * 32 + 255) / 256;

    // conv1: 256 -> 4x64 concat, relu
    gemm(x, 256, c1_wl, nullptr, xl, 256, 0, 256, 256, 0);
    gemm(x, 256, c1_wr, nullptr, xr, 256, 0, 256, 256, 0);
    gat_agg<4, 64, true><<<gat_blocks, 256>>>(xl, xr, c1_att, c1_b, off, esrc, y, n);

    // conv2: 256 -> 2x64 concat, relu
    gemm(y, 256, c2_wl, nullptr, xl, 128, 0, 128, 256, 0);
    gemm(y, 256, c2_wr, nullptr, xr, 128, 0, 128, 256, 0);
    gat_agg<2, 64, true><<<gat_blocks, 256>>>(xl, xr, c2_att, c2_b, off, esrc, x, n);

    // conv3: 128 -> 1x256, single head (mean == identity), no relu
    gemm(x, 128, c3_wl, nullptr, xl, 256, 0, 256, 128, 0);
    gemm(x, 128, c3_wr, nullptr, xr, 256, 0, 256, 128, 0);
    gat_agg<1, 256, false><<<gat_blocks, 256>>>(xl, xr, c3_att, c3_b, off, esrc, y, n);

    // enhancer MLP + LayerNorm
    gemm(y,  256, en_w1, en_b1, h1, 512, 0, 512, 256, 1);
    gemm(h1, 512, en_w2, en_b2, x,  256, 0, 256, 512, 0);
    k_ln<<<gat_blocks, 256>>>(x, ln_g, ln_b, (float*)d_out, n);
}